// round 7
// baseline (speedup 1.0000x reference)
#include <cuda_runtime.h>
#include <math.h>
#include <cstdint>

// Problem constants (fixed by setup_inputs)
#define B_  2
#define T_  8
#define M_  900
#define H_  27
#define W_  27
#define D_  1024
#define PATCH_ 14

#define NBLK (B_ * M_)                    // 1800 blocks, one per (b, m)
#define NPAIR_DENOM (B_ * (T_ - 1) * M_)  // 12600, mean denominator
#define ROW_BYTES (D_ * 4)                // 4096

__device__ float        g_partials[NBLK];
__device__ unsigned int g_done = 0;   // reset by the last block each launch

__device__ __forceinline__ uint32_t smem_u32(const void* p) {
    uint32_t a;
    asm("{ .reg .u64 t; cvta.to.shared.u64 t, %1; cvt.u32.u64 %0, t; }"
        : "=r"(a) : "l"(p));
    return a;
}

// L1 over 4 dims: abs folds into FADD source modifiers
__device__ __forceinline__ float l1_4(const float4& a, const float4& b)
{
    float d0 = a.x - b.x, d1 = a.y - b.y, d2 = a.z - b.z, d3 = a.w - b.w;
    return (fabsf(d0) + fabsf(d1)) + (fabsf(d2) + fabsf(d3));
}

__global__ __launch_bounds__(256, 6)
void gather_l1_tma_kernel(const float* __restrict__ features,
                          const float* __restrict__ tracks,
                          const int* __restrict__ vis,   // bool stored as int32
                          float* __restrict__ out)
{
    __shared__ __align__(16) float s_rows[T_][D_];   // 32KB TMA destination
    __shared__ __align__(8)  unsigned long long s_mbar;
    __shared__ int   s_nn[T_];
    __shared__ float s_fv[T_];
    __shared__ float s_warp[8];
    __shared__ bool  s_is_last;

    const int bm   = blockIdx.x;         // 0..1799
    const int b    = bm / M_;
    const int m    = bm - b * M_;
    const int tid  = threadIdx.x;        // 256 threads
    const int lane = tid & 31;
    const int wid  = tid >> 5;

    const uint32_t mbar = smem_u32(&s_mbar);

    // --- Threads 0..7 compute NN index + visibility for frame t=tid
    if (tid < T_) {
        const int t = tid;
        const float2 tr = *(const float2*)(tracks
            + (unsigned)(((b * T_ + t) * M_ + m) * 2));
        // nearest patch center c_j = 14j+7 -> j = clamp(floor(x/14), 0, 26)
        int j = (int)floorf(tr.x * (1.0f / PATCH_));
        int i = (int)floorf(tr.y * (1.0f / PATCH_));
        j = min(W_ - 1, max(0, j));
        i = min(H_ - 1, max(0, i));
        s_nn[t] = i * W_ + j;
        s_fv[t] = (float)vis[(unsigned)((b * T_ + t) * M_ + m)];
    }
    if (tid == 0) {
        asm volatile("mbarrier.init.shared.b64 [%0], %1;"
                     :: "r"(mbar), "r"(1u) : "memory");
        asm volatile("fence.proxy.async.shared::cta;" ::: "memory");
    }
    __syncthreads();

    // --- One thread issues 8 bulk async copies (4KB rows) + expect_tx
    if (tid == 0) {
        asm volatile("mbarrier.arrive.expect_tx.shared.b64 _, [%0], %1;"
                     :: "r"(mbar), "r"((uint32_t)(T_ * ROW_BYTES)) : "memory");
#pragma unroll
        for (int t = 0; t < T_; t++) {
            const float* src = features
                + ((unsigned)((b * T_ + t) * (H_ * W_) + s_nn[t]) << 10);
            uint32_t dst = smem_u32(&s_rows[t][0]);
            asm volatile(
                "cp.async.bulk.shared::cluster.global.mbarrier::complete_tx::bytes "
                "[%0], [%1], %2, [%3];"
                :: "r"(dst), "l"(src), "r"((uint32_t)ROW_BYTES), "r"(mbar)
                : "memory");
        }
    }

    // --- All threads wait for the 32KB to land
    {
        uint32_t done;
        asm volatile(
            "{\n\t.reg .pred p;\n\t"
            "mbarrier.try_wait.parity.acquire.cta.shared::cta.b64 p, [%1], %2;\n\t"
            "selp.b32 %0, 1, 0, p;\n\t}"
            : "=r"(done) : "r"(mbar), "r"(0u) : "memory");
        if (!done) {
            asm volatile(
                "{\n\t.reg .pred P1;\n\t"
                "WL_%=:\n\t"
                "mbarrier.try_wait.parity.acquire.cta.shared::cta.b64 P1, [%0], %1, 0x989680;\n\t"
                "@P1 bra.uni WD_%=;\n\t"
                "bra.uni WL_%=;\n\t"
                "WD_%=:\n\t}"
                :: "r"(mbar), "r"(0u) : "memory");
        }
    }

    // --- Streaming compute from smem (live set: pf0, prev, cur)
    float fv[T_];
#pragma unroll
    for (int t = 0; t < T_; t++) fv[t] = s_fv[t];   // LDS broadcast

    float4 p0   = ((const float4*)s_rows[0])[tid];
    float4 prev = ((const float4*)s_rows[1])[tid];
    float  l01  = l1_4(p0, prev);
    float  m01  = fv[0] * fv[1];
    float acc_c = m01 * l01;          // consec pair t=0
    float acc_r = m01 * l01;          // ref pair t=0 (same pair)
#pragma unroll
    for (int t = 1; t < T_ - 1; t++) {
        float4 cur = ((const float4*)s_rows[t + 1])[tid];
        acc_c = fmaf(fv[t] * fv[t + 1], l1_4(prev, cur), acc_c);
        acc_r = fmaf(fv[0] * fv[t + 1], l1_4(p0,   cur), acc_r);
        prev = cur;
    }
    float acc = acc_c + acc_r;

    // --- Block reduction: warp shuffle, then 8 warp sums via shared
#pragma unroll
    for (int o = 16; o > 0; o >>= 1)
        acc += __shfl_down_sync(0xffffffffu, acc, o);

    if (lane == 0) s_warp[wid] = acc;
    __syncthreads();

    if (tid == 0) {
        float s = 0.0f;
#pragma unroll
        for (int w = 0; w < 8; w++) s += s_warp[w];
        g_partials[bm] = s;
        __threadfence();
        unsigned int prev_cnt = atomicAdd(&g_done, 1u);
        s_is_last = (prev_cnt == NBLK - 1);
    }
    __syncthreads();

    // --- Last block reduces all partials (fixed order -> deterministic)
    if (s_is_last) {
        double dacc = 0.0;
#pragma unroll
        for (int k = 0; k < (NBLK + 255) / 256; k++) {
            int i = k * 256 + tid;
            if (i < NBLK) dacc += (double)g_partials[i];
        }
#pragma unroll
        for (int o = 16; o > 0; o >>= 1)
            dacc += __shfl_down_sync(0xffffffffu, dacc, o);

        __shared__ double s_dwarp[8];
        if (lane == 0) s_dwarp[wid] = dacc;
        __syncthreads();
        if (tid == 0) {
            double s = 0.0;
#pragma unroll
            for (int w = 0; w < 8; w++) s += s_dwarp[w];
            out[0] = (float)(0.01 * s / (double)NPAIR_DENOM);
            g_done = 0;                  // reset for next graph replay
        }
    }
}

extern "C" void kernel_launch(void* const* d_in, const int* in_sizes, int n_in,
                              void* d_out, int out_size)
{
    const float* features = (const float*)d_in[0];  // [B*T, H*W, D] f32
    const float* tracks   = (const float*)d_in[1];  // [B, T, M, 2]  f32
    const int*   vis      = (const int*)d_in[2];    // [B, T, M]     bool->int32
    float*       out      = (float*)d_out;

    gather_l1_tma_kernel<<<NBLK, 256>>>(features, tracks, vis, out);
}

// round 8
// speedup vs baseline: 1.2225x; 1.2225x over previous
#include <cuda_runtime.h>
#include <math.h>

// Problem constants (fixed by setup_inputs)
#define B_  2
#define T_  8
#define M_  900
#define H_  27
#define W_  27
#define D_  1024
#define PATCH_ 14

#define NBLK   M_                          // 900 blocks, one per track m (both batches)
#define NPAIR_DENOM (B_ * (T_ - 1) * M_)   // 12600, mean denominator

__device__ float        g_partials[NBLK];
__device__ unsigned int g_done = 0;   // reset by the last block each launch

// L1 over 4 dims: abs folds into FADD source modifiers
__device__ __forceinline__ float l1_4(const float4& a, const float4& b)
{
    float d0 = a.x - b.x, d1 = a.y - b.y, d2 = a.z - b.z, d3 = a.w - b.w;
    return (fabsf(d0) + fabsf(d1)) + (fabsf(d2) + fabsf(d3));
}

__global__ __launch_bounds__(256, 6)      // 42-reg budget -> 6 blocks/SM, ~1.01 waves
void gather_l1_onewave_kernel(const float* __restrict__ features,
                              const float* __restrict__ tracks,
                              const int* __restrict__ vis,   // bool stored as int32
                              float* __restrict__ out)
{
    const int m    = blockIdx.x;          // 0..899
    const int tid  = threadIdx.x;         // 256 threads = 1024 floats / 4
    const int lane = tid & 31;
    const int wid  = tid >> 5;

    // --- Lanes 0..15 of every warp: lane<8 -> (b=0, t=lane); lane>=8 -> (b=1, t=lane-8).
    // Both batches' indices resolve up front; addresses identical across warps (L1 bcast).
    int my_nn = 0, my_vis = 0;
    if (lane < 2 * T_) {
        const int bb = lane >> 3;         // 0 or 1
        const int t  = lane & 7;
        const float2 tr = *(const float2*)(tracks
            + (unsigned)(((bb * T_ + t) * M_ + m) * 2));
        // nearest patch center c_j = 14j+7 -> j = clamp(floor(x/14), 0, 26)
        int j = (int)floorf(tr.x * (1.0f / PATCH_));
        int i = (int)floorf(tr.y * (1.0f / PATCH_));
        j = min(W_ - 1, max(0, j));
        i = min(H_ - 1, max(0, i));
        my_nn  = i * W_ + j;
        my_vis = vis[(unsigned)((bb * T_ + t) * M_ + m)];
    }

    float acc = 0.0f;

#pragma unroll
    for (int bb = 0; bb < B_; bb++) {
        int   nn[T_];
        float fv[T_];
#pragma unroll
        for (int t = 0; t < T_; t++) {
            nn[t] = __shfl_sync(0xffffffffu, my_nn, bb * T_ + t);
            fv[t] = (float)__shfl_sync(0xffffffffu, my_vis, bb * T_ + t);
        }

        // Gather 8 rows; 8 independent LDG.128 per thread, 32-bit offsets.
        float4 pf[T_];
#pragma unroll
        for (int t = 0; t < T_; t++) {
            unsigned off = ((unsigned)((bb * T_ + t) * (H_ * W_) + nn[t]) << 10)
                         + ((unsigned)tid << 2);
            pf[t] = *(const float4*)(features + off);
        }

        // 13 distinct pairs; pair (0,1) serves both consec and ref terms.
        float l01 = l1_4(pf[0], pf[1]);
        float m01 = fv[0] * fv[1];
        float acc_c = m01 * l01;
        float acc_r = m01 * l01;
#pragma unroll
        for (int t = 1; t < T_ - 1; t++) {
            acc_c = fmaf(fv[t] * fv[t + 1], l1_4(pf[t], pf[t + 1]), acc_c);
            acc_r = fmaf(fv[0] * fv[t + 1], l1_4(pf[0], pf[t + 1]), acc_r);
        }
        acc += acc_c + acc_r;             // fixed order -> deterministic
    }

    // --- Block reduction: warp shuffle, then 8 warp sums via shared
#pragma unroll
    for (int o = 16; o > 0; o >>= 1)
        acc += __shfl_down_sync(0xffffffffu, acc, o);

    __shared__ float s_warp[8];
    if (lane == 0) s_warp[wid] = acc;
    __syncthreads();

    __shared__ bool s_is_last;
    if (tid == 0) {
        float s = 0.0f;
#pragma unroll
        for (int w = 0; w < 8; w++) s += s_warp[w];
        g_partials[m] = s;
        __threadfence();
        unsigned int prev = atomicAdd(&g_done, 1u);
        s_is_last = (prev == NBLK - 1);
    }
    __syncthreads();

    // --- Last block reduces all partials (fixed order -> deterministic)
    if (s_is_last) {
        double dacc = 0.0;
#pragma unroll
        for (int k = 0; k < (NBLK + 255) / 256; k++) {
            int i = k * 256 + tid;
            if (i < NBLK) dacc += (double)g_partials[i];
        }
#pragma unroll
        for (int o = 16; o > 0; o >>= 1)
            dacc += __shfl_down_sync(0xffffffffu, dacc, o);

        __shared__ double s_dwarp[8];
        if (lane == 0) s_dwarp[wid] = dacc;
        __syncthreads();
        if (tid == 0) {
            double s = 0.0;
#pragma unroll
            for (int w = 0; w < 8; w++) s += s_dwarp[w];
            out[0] = (float)(0.01 * s / (double)NPAIR_DENOM);
            g_done = 0;                   // reset for next graph replay
        }
    }
}

extern "C" void kernel_launch(void* const* d_in, const int* in_sizes, int n_in,
                              void* d_out, int out_size)
{
    const float* features = (const float*)d_in[0];  // [B*T, H*W, D] f32
    const float* tracks   = (const float*)d_in[1];  // [B, T, M, 2]  f32
    const int*   vis      = (const int*)d_in[2];    // [B, T, M]     bool->int32
    float*       out      = (float*)d_out;

    gather_l1_onewave_kernel<<<NBLK, 256>>>(features, tracks, vis, out);
}